// round 9
// baseline (speedup 1.0000x reference)
#include <cuda_runtime.h>
#include <cstddef>

#define NBLK   148
#define NTHR   512
#define NWARPS_DEC (NBLK * 16)   // 2368
#define NPAIRS 65536             // 131072 rows / 2
#define MDIM   450

// L2-resident split of dec_W2 (pairs of rows; 3600B/pair)
#define PR_RES   26624           // 26624*3600 = 95,846,400 B kept evict-normal
#define PF_LINES 748800u         // exact resident 128B-line count
#define PF_PER_PHASE 187200u     // PF_LINES / 4 phases
#define PF_THREADS 60928u        // (148-29) blocks * 512 threads

// Scratch (device globals; no allocation)
__device__ __align__(16) float g_Fpart[128 * 128];
__device__ __align__(16) float g_feat[452];
__device__ __align__(16) float g_h[452];
__device__ __align__(16) float g_feat2[452];
__device__ __align__(16) float g_h2[452];

// Grid barrier (monotonic generation -> graph-replay safe)
__device__ unsigned g_count = 0;
__device__ volatile unsigned g_gen = 0;

__device__ __forceinline__ void grid_bar()
{
    __syncthreads();
    if (threadIdx.x == 0) {
        const unsigned gen = g_gen;
        __threadfence();
        if (atomicAdd(&g_count, 1u) == (unsigned)gridDim.x - 1u) {
            atomicExch(&g_count, 0u);
            __threadfence();
            g_gen = gen + 1u;
        } else {
            while (g_gen == gen) { }
            __threadfence();
        }
    }
    __syncthreads();
}

// Bounded L2 prefetch of the resident region only. phase in [0,4).
// Max byte touched = (PF_LINES-1)*128+127 < 95.9MB << 236MB allocation.
__device__ __forceinline__ void pf_resident(const float* dW2, int phase)
{
    const unsigned base = phase * PF_PER_PHASE;
    const unsigned hi   = base + PF_PER_PHASE;           // <= PF_LINES
    const unsigned my   = (blockIdx.x - 29) * NTHR + threadIdx.x; // 0..60927
    const char* p = (const char*)dW2;
    #pragma unroll
    for (unsigned k = 0; k < 4; ++k) {
        unsigned line = base + my + k * PF_THREADS;
        if (line < hi)
            asm volatile("prefetch.global.L2 [%0];" :: "l"(p + (size_t)line * 128));
    }
}

// Warp-per-row 450x450 matvec: vout = [relu](W @ vin + b). Blocks 0..28.
__device__ __forceinline__ void mv450_stage(const float* __restrict__ W,
                                            const float* __restrict__ b,
                                            const float* __restrict__ vin_g,
                                            float* __restrict__ vout_g,
                                            bool do_relu, float* sh)
{
    const int tid = threadIdx.x;
    if (tid < MDIM) sh[tid] = __ldcg(vin_g + tid);
    __syncthreads();

    const int wid  = tid >> 5;
    const int lane = tid & 31;
    const int row  = blockIdx.x * 16 + wid;
    if (row < MDIM) {
        const float2* wr = reinterpret_cast<const float2*>(W + (size_t)row * MDIM);
        const float2* sv = reinterpret_cast<const float2*>(sh);
        float acc = 0.f;
        #pragma unroll
        for (int j = 0; j < 7; ++j) {
            const float2 w = __ldg(wr + lane + 32 * j);
            const float2 v = sv[lane + 32 * j];
            acc += w.x * v.x + w.y * v.y;
        }
        if (lane == 0) {
            const float2 w = __ldg(wr + 224);
            const float2 v = sv[224];
            acc += w.x * v.x + w.y * v.y;
        }
        #pragma unroll
        for (int o = 16; o; o >>= 1) acc += __shfl_xor_sync(0xFFFFFFFFu, acc, o);
        if (lane == 0) {
            float r = acc + __ldg(b + row);
            vout_g[row] = do_relu ? fmaxf(r, 0.f) : r;
        }
    }
}

__global__ void __launch_bounds__(NTHR, 1)
fused_kernel(const float* __restrict__ x,   const float* __restrict__ TwE,
             const float* __restrict__ PE,  const float* __restrict__ CE,
             const float* __restrict__ mE,
             const float* __restrict__ eW1, const float* __restrict__ eb1,
             const float* __restrict__ eW2, const float* __restrict__ eb2,
             const float* __restrict__ dW1, const float* __restrict__ db1,
             const float* __restrict__ dW2, const float* __restrict__ db2,
             float* __restrict__ out, int xoff)
{
    __shared__ float sh[10240];            // 40KB, reused per stage
    const int tid  = threadIdx.x;
    const int wid  = tid >> 5;
    const int lane = tid & 31;
    const int blk  = blockIdx.x;

    // ===== Stage 1: f partials. 128 blocks x 8 tp-rows, 512 threads. =====
    // Warp = (row-pair pr=wid&3 -> rows 2pr,2pr+1 ; chunk ch=wid>>2 -> 32 c's).
    if (blk < 128) {
        float* sx = sh;                    // [8][128] x rows (1024 floats)
        float* sp = sh + 1024;             // [4 chunks][8 rows][128 i] (4096)
        sx[tid]       = x[xoff + blk * 1024 + tid];
        sx[tid + 512] = x[xoff + blk * 1024 + tid + 512];
        __syncthreads();

        const int pr = wid & 3;
        const int ch = wid >> 2;
        const int i0 = lane * 4;
        const int r0 = pr * 2, r1 = r0 + 1;
        float4 a0 = {0,0,0,0}, a1 = {0,0,0,0};
        const int cb = ch * 32;
        #pragma unroll
        for (int cc = 0; cc < 32; ++cc) {
            const int c = cb + cc;
            const float4 ce = *reinterpret_cast<const float4*>(CE + c * 128 + i0);
            const float x0 = sx[r0 * 128 + c];
            const float x1 = sx[r1 * 128 + c];
            a0.x += x0 * ce.x; a0.y += x0 * ce.y; a0.z += x0 * ce.z; a0.w += x0 * ce.w;
            a1.x += x1 * ce.x; a1.y += x1 * ce.y; a1.z += x1 * ce.z; a1.w += x1 * ce.w;
        }
        *reinterpret_cast<float4*>(sp + (ch * 8 + r0) * 128 + i0) = a0;
        *reinterpret_cast<float4*>(sp + (ch * 8 + r1) * 128 + i0) = a1;
        __syncthreads();

        // each thread handles rows ra and ra+4
        const int ra = tid >> 7;           // 0..3
        const int i  = tid & 127;
        float sa = 0.f, sb = 0.f;
        #pragma unroll
        for (int c2 = 0; c2 < 4; ++c2) {
            sa += sp[(c2 * 8 + ra)     * 128 + i];
            sb += sp[(c2 * 8 + ra + 4) * 128 + i];
        }
        {
            const int gra = blk * 8 + ra;
            const int grb = gra + 4;
            sa *= __ldg(PE + (gra & 255) * 128 + i) * __ldg(TwE + (gra >> 8) * 128 + i);
            sb *= __ldg(PE + (grb & 255) * 128 + i) * __ldg(TwE + (grb >> 8) * 128 + i);
        }
        sh[ra * 128 + i]       = sa;       // overwrite sx (done with it)
        sh[(ra + 4) * 128 + i] = sb;
        __syncthreads();
        if (tid < 128) {
            float t2 = 0.f;
            #pragma unroll
            for (int r = 0; r < 8; ++r) t2 += sh[r * 128 + tid];
            g_Fpart[blk * 128 + tid] = t2;
        }
    }
    grid_bar();

    // ===== Stage 2: feat = mE @ f (blocks 0..28); others prefetch phase 0 =====
    if (blk < 29) {
        float* tmp = sh + 1024;
        {
            const int grp = tid >> 7;      // 0..3, each sums 32 partials
            const int i   = tid & 127;
            float s = 0.f;
            #pragma unroll
            for (int b = 0; b < 32; ++b)
                s += __ldcg(&g_Fpart[(grp * 32 + b) * 128 + i]);
            tmp[grp * 128 + i] = s;
        }
        __syncthreads();
        if (tid < 128)
            sh[tid] = tmp[tid] + tmp[128 + tid] + tmp[256 + tid] + tmp[384 + tid];
        __syncthreads();
        const int row = blk * 16 + wid;
        if (row < MDIM) {
            const float* r = mE + row * 128;
            float acc = __ldg(r + lane)       * sh[lane]
                      + __ldg(r + lane + 32)  * sh[lane + 32]
                      + __ldg(r + lane + 64)  * sh[lane + 64]
                      + __ldg(r + lane + 96)  * sh[lane + 96];
            #pragma unroll
            for (int o = 16; o; o >>= 1) acc += __shfl_xor_sync(0xFFFFFFFFu, acc, o);
            if (lane == 0) g_feat[row] = acc;
        }
    } else {
        pf_resident(dW2, 0);
    }
    grid_bar();

    // ===== Stages 3..5: 450x450 chain (blocks 0..28); others prefetch =====
    if (blk < 29) mv450_stage(eW1, eb1, g_feat, g_h, true, sh);
    else pf_resident(dW2, 1);
    grid_bar();
    if (blk < 29) mv450_stage(eW2, eb2, g_h, g_feat2, false, sh);
    else pf_resident(dW2, 2);
    grid_bar();
    if (blk < 29) mv450_stage(dW1, db1, g_feat2, g_h2, true, sh);
    else pf_resident(dW2, 3);
    grid_bar();

    // ===== Stage 6: out = dec_W2 @ h2 + db2 (131072 x 450) =====
    // v-vector hoisted to registers (no LDS in the hot loop).
    {
        for (int i = tid; i < 900; i += NTHR)
            sh[i] = __ldcg(&g_h2[(i < 450) ? i : (i - 450)]);
        __syncthreads();
        const float4* VV = reinterpret_cast<const float4*>(sh);
        const float4 v0 = VV[lane];
        const float4 v1 = VV[lane + 32];
        const float4 v2 = VV[lane + 64];
        const float4 v3 = VV[lane + 96];   // straddle at lane 16
        const float4 v4 = VV[lane + 128];
        const float4 v5 = VV[lane + 160];
        const float4 v6 = VV[lane + 192];
        const float4 vt = VV[224];         // tail (row1), used by lane 0

        const int gw = blk * 16 + wid;     // 0..2367
        const bool lo16 = (lane < 16);

        for (int pr = gw; pr < NPAIRS; pr += NWARPS_DEC) {
            const float4* wr = reinterpret_cast<const float4*>(dW2 + (size_t)pr * 900);
            const bool res = (pr < PR_RES);
            float4 w0 = res ? __ldg(wr + lane)       : __ldcs(wr + lane);
            float4 w1 = res ? __ldg(wr + lane + 32)  : __ldcs(wr + lane + 32);
            float4 w2 = res ? __ldg(wr + lane + 64)  : __ldcs(wr + lane + 64);
            float4 w3 = res ? __ldg(wr + lane + 96)  : __ldcs(wr + lane + 96);
            float4 w4 = res ? __ldg(wr + lane + 128) : __ldcs(wr + lane + 128);
            float4 w5 = res ? __ldg(wr + lane + 160) : __ldcs(wr + lane + 160);
            float4 w6 = res ? __ldg(wr + lane + 192) : __ldcs(wr + lane + 192);
            float4 wt;
            if (lane == 0) wt = res ? __ldg(wr + 224) : __ldcs(wr + 224);

            float acc0 = w0.x*v0.x + w0.y*v0.y + w0.z*v0.z + w0.w*v0.w
                       + w1.x*v1.x + w1.y*v1.y + w1.z*v1.z + w1.w*v1.w
                       + w2.x*v2.x + w2.y*v2.y + w2.z*v2.z + w2.w*v2.w;
            float acc1 = w4.x*v4.x + w4.y*v4.y + w4.z*v4.z + w4.w*v4.w
                       + w5.x*v5.x + w5.y*v5.y + w5.z*v5.z + w5.w*v5.w
                       + w6.x*v6.x + w6.y*v6.y + w6.z*v6.z + w6.w*v6.w;
            {   // straddle: float4 idx lane+96; elements 448..451 sit at lane 16
                const float dlo = w3.x*v3.x + w3.y*v3.y;
                const float dhi = w3.z*v3.z + w3.w*v3.w;
                acc0 += lo16 ? (dlo + dhi) : ((lane == 16) ? dlo : 0.f);
                acc1 += (!lo16 && lane != 16) ? (dlo + dhi) : ((lane == 16) ? dhi : 0.f);
            }
            if (lane == 0)
                acc1 += wt.x*vt.x + wt.y*vt.y + wt.z*vt.z + wt.w*vt.w;

            // 5-shuffle dual reduction: lane0 <- sum(acc0), lane16 <- sum(acc1)
            float z = lo16 ? acc0 : acc1;
            z += __shfl_xor_sync(0xFFFFFFFFu, lo16 ? acc1 : acc0, 16);
            #pragma unroll
            for (int o = 8; o; o >>= 1) z += __shfl_xor_sync(0xFFFFFFFFu, z, o);

            if (lane == 0)  out[2 * pr]     = z + __ldg(db2 + 2 * pr);
            if (lane == 16) out[2 * pr + 1] = z + __ldg(db2 + 2 * pr + 1);
        }
    }
}

// ---------------------------------------------------------------------------
// Inputs: x, t, TwE, PE, CE, mE, ext_W1, ext_b1, ext_W2, ext_b2,
//         dec_W1, dec_b1, dec_W2, dec_b2
// ---------------------------------------------------------------------------
extern "C" void kernel_launch(void* const* d_in, const int* in_sizes, int n_in,
                              void* d_out, int out_size)
{
    const float* x   = (const float*)d_in[0];
    const float* TwE = (const float*)d_in[2];
    const float* PE  = (const float*)d_in[3];
    const float* CE  = (const float*)d_in[4];
    const float* mE  = (const float*)d_in[5];
    const float* eW1 = (const float*)d_in[6];
    const float* eb1 = (const float*)d_in[7];
    const float* eW2 = (const float*)d_in[8];
    const float* eb2 = (const float*)d_in[9];
    const float* dW1 = (const float*)d_in[10];
    const float* db1 = (const float*)d_in[11];
    const float* dW2 = (const float*)d_in[12];
    const float* db2 = (const float*)d_in[13];
    float* out = (float*)d_out;

    const int xoff = in_sizes[0] - 4 * 256 * 128;

    fused_kernel<<<NBLK, NTHR>>>(x, TwE, PE, CE, mE,
                                 eW1, eb1, eW2, eb2,
                                 dW1, db1, dW2, db2,
                                 out, xoff);
    (void)n_in; (void)out_size;
}

// round 10
// speedup vs baseline: 1.0040x; 1.0040x over previous
#include <cuda_runtime.h>
#include <cstddef>
#include <cstdint>

#define NBLK   148
#define NTHR   1024
#define NPAIRS 65536             // 131072 rows / 2
#define MDIM   450

// dec work split
#define PAIRS_PER_BLK 443        // ceil(65536/148)
#define CHUNK  31                // pairs per pipeline chunk (fits 2 bufs in smem)
#define PAIR_BYTES 3600

// smem layout (bytes)
#define BUF0_OFF   0
#define BUF1_OFF   111600        // 31*3600
#define V_OFF      223200        // 904 floats
#define MB_OFF     226816        // 2 x 8B mbarriers
#define SMEM_BYTES 226880

// L2-resident split of dec_W2
#define PR_RES   26624           // first 26624 pairs (95.8MB) evict-normal
#define PF_LINES 748800u         // resident 128B-line count
#define PF_PER_PHASE 187200u
#define PF_THREADS 136192u       // 133 blocks * 1024 threads

// Scratch (device globals; no allocation)
__device__ __align__(16) float g_Fpart[128 * 128];
__device__ __align__(16) float g_feat[452];
__device__ __align__(16) float g_h[452];
__device__ __align__(16) float g_feat2[452];
__device__ __align__(16) float g_h2[452];

// Grid barrier (monotonic generation -> graph-replay safe)
__device__ unsigned g_count = 0;
__device__ volatile unsigned g_gen = 0;

__device__ __forceinline__ void grid_bar()
{
    __syncthreads();
    if (threadIdx.x == 0) {
        const unsigned gen = g_gen;
        __threadfence();
        if (atomicAdd(&g_count, 1u) == (unsigned)gridDim.x - 1u) {
            atomicExch(&g_count, 0u);
            __threadfence();
            g_gen = gen + 1u;
        } else {
            while (g_gen == gen) { }
            __threadfence();
        }
    }
    __syncthreads();
}

// Bounded L2 prefetch of the resident region only. phase in [0,4).
__device__ __forceinline__ void pf_resident(const float* dW2, int phase)
{
    const unsigned base = phase * PF_PER_PHASE;
    const unsigned hi   = base + PF_PER_PHASE;           // <= PF_LINES
    const unsigned my   = (blockIdx.x - 15) * NTHR + threadIdx.x;
    const char* p = (const char*)dW2;
    #pragma unroll
    for (unsigned k = 0; k < 2; ++k) {
        unsigned line = base + my + k * PF_THREADS;
        if (line < hi)
            asm volatile("prefetch.global.L2 [%0];" :: "l"(p + (size_t)line * 128));
    }
}

// Warp-per-row 450x450 matvec: blocks 0..14 (32 warps each).
__device__ __forceinline__ void mv450_stage(const float* __restrict__ W,
                                            const float* __restrict__ b,
                                            const float* __restrict__ vin_g,
                                            float* __restrict__ vout_g,
                                            bool do_relu, float* sh)
{
    const int tid = threadIdx.x;
    if (tid < MDIM) sh[tid] = __ldcg(vin_g + tid);
    __syncthreads();

    const int wid  = tid >> 5;
    const int lane = tid & 31;
    const int row  = blockIdx.x * 32 + wid;
    if (row < MDIM) {
        const float2* wr = reinterpret_cast<const float2*>(W + (size_t)row * MDIM);
        const float2* sv = reinterpret_cast<const float2*>(sh);
        float acc = 0.f;
        #pragma unroll
        for (int j = 0; j < 7; ++j) {
            const float2 w = __ldg(wr + lane + 32 * j);
            const float2 v = sv[lane + 32 * j];
            acc += w.x * v.x + w.y * v.y;
        }
        if (lane == 0) {
            const float2 w = __ldg(wr + 224);
            const float2 v = sv[224];
            acc += w.x * v.x + w.y * v.y;
        }
        #pragma unroll
        for (int o = 16; o; o >>= 1) acc += __shfl_xor_sync(0xFFFFFFFFu, acc, o);
        if (lane == 0) {
            float r = acc + __ldg(b + row);
            vout_g[row] = do_relu ? fmaxf(r, 0.f) : r;
        }
    }
}

// ---- mbarrier / bulk-copy PTX helpers ----
__device__ __forceinline__ unsigned smem_addr(const void* p)
{
    return (unsigned)__cvta_generic_to_shared(p);
}
__device__ __forceinline__ void mbar_init(unsigned a)
{
    asm volatile("mbarrier.init.shared.b64 [%0], 1;" :: "r"(a) : "memory");
}
__device__ __forceinline__ void bulk_ld(unsigned dst, const void* src,
                                        unsigned bytes, unsigned mbar,
                                        bool stream, uint64_t pol)
{
    // arrive+expect_tx then issue the bulk copy completing on the same mbarrier
    asm volatile("mbarrier.arrive.expect_tx.shared.b64 _, [%0], %1;"
                 :: "r"(mbar), "r"(bytes) : "memory");
    if (stream) {
        asm volatile("cp.async.bulk.shared::cta.global.mbarrier::complete_tx::bytes"
                     ".L2::cache_hint [%0], [%1], %2, [%3], %4;"
                     :: "r"(dst), "l"(src), "r"(bytes), "r"(mbar), "l"(pol) : "memory");
    } else {
        asm volatile("cp.async.bulk.shared::cta.global.mbarrier::complete_tx::bytes"
                     " [%0], [%1], %2, [%3];"
                     :: "r"(dst), "l"(src), "r"(bytes), "r"(mbar) : "memory");
    }
}
__device__ __forceinline__ void mbar_wait(unsigned a, unsigned parity)
{
    unsigned done = 0;
    while (!done) {
        asm volatile("{\n\t.reg .pred p;\n\t"
                     "mbarrier.try_wait.parity.shared.b64 p, [%1], %2;\n\t"
                     "selp.b32 %0, 1, 0, p;\n\t}"
                     : "=r"(done) : "r"(a), "r"(parity) : "memory");
    }
}
__device__ __forceinline__ void fence_async_smem()
{
    asm volatile("fence.proxy.async.shared::cta;" ::: "memory");
}

__global__ void __launch_bounds__(NTHR, 1)
fused_kernel(const float* __restrict__ x,   const float* __restrict__ TwE,
             const float* __restrict__ PE,  const float* __restrict__ CE,
             const float* __restrict__ mE,
             const float* __restrict__ eW1, const float* __restrict__ eb1,
             const float* __restrict__ eW2, const float* __restrict__ eb2,
             const float* __restrict__ dW1, const float* __restrict__ db1,
             const float* __restrict__ dW2, const float* __restrict__ db2,
             float* __restrict__ out, int xoff)
{
    extern __shared__ __align__(16) char smem[];
    float* sh = reinterpret_cast<float*>(smem);     // prologue scratch (aliases buf0)

    const int tid  = threadIdx.x;
    const int wid  = tid >> 5;
    const int lane = tid & 31;
    const int blk  = blockIdx.x;

    // ===== Stage 1: f partials. 128 blocks x 8 tp-rows, 1024 threads. =====
    if (blk < 128) {
        float* sx = sh;                    // [8][128]
        float* sp = sh + 1024;             // [8 chunks][8 rows][128 i]
        sx[tid] = x[xoff + blk * 1024 + tid];
        __syncthreads();

        const int pr = wid & 3;
        const int ch = wid >> 2;
        const int i0 = lane * 4;
        const int r0 = pr * 2, r1 = r0 + 1;
        float4 a0 = {0,0,0,0}, a1 = {0,0,0,0};
        const int cb = ch * 16;
        #pragma unroll
        for (int cc = 0; cc < 16; ++cc) {
            const int c = cb + cc;
            const float4 ce = *reinterpret_cast<const float4*>(CE + c * 128 + i0);
            const float x0 = sx[r0 * 128 + c];
            const float x1 = sx[r1 * 128 + c];
            a0.x += x0 * ce.x; a0.y += x0 * ce.y; a0.z += x0 * ce.z; a0.w += x0 * ce.w;
            a1.x += x1 * ce.x; a1.y += x1 * ce.y; a1.z += x1 * ce.z; a1.w += x1 * ce.w;
        }
        __syncthreads();                   // sx no longer needed before sp write? sp disjoint; sync for safety of reuse below
        *reinterpret_cast<float4*>(sp + (ch * 8 + r0) * 128 + i0) = a0;
        *reinterpret_cast<float4*>(sp + (ch * 8 + r1) * 128 + i0) = a1;
        __syncthreads();

        const int row = tid >> 7;          // 0..7
        const int i   = tid & 127;
        float s = 0.f;
        #pragma unroll
        for (int c2 = 0; c2 < 8; ++c2) s += sp[(c2 * 8 + row) * 128 + i];
        const int gr = blk * 8 + row;
        s *= __ldg(PE + (gr & 255) * 128 + i) * __ldg(TwE + (gr >> 8) * 128 + i);
        __syncthreads();
        sh[tid] = s;
        __syncthreads();
        if (tid < 128) {
            float t2 = 0.f;
            #pragma unroll
            for (int r = 0; r < 8; ++r) t2 += sh[r * 128 + tid];
            g_Fpart[blk * 128 + tid] = t2;
        }
    }
    grid_bar();

    // ===== Stage 2: feat = mE @ f (blocks 0..14); others prefetch =====
    if (blk < 15) {
        float* tmp = sh + 1024;
        {
            const int grp = tid >> 7;      // 0..7, each sums 16 partials
            const int i   = tid & 127;
            float s = 0.f;
            #pragma unroll
            for (int b = 0; b < 16; ++b)
                s += __ldcg(&g_Fpart[(grp * 16 + b) * 128 + i]);
            tmp[grp * 128 + i] = s;
        }
        __syncthreads();
        if (tid < 128) {
            float s = 0.f;
            #pragma unroll
            for (int g = 0; g < 8; ++g) s += tmp[g * 128 + tid];
            sh[tid] = s;
        }
        __syncthreads();
        const int row = blk * 32 + wid;
        if (row < MDIM) {
            const float* r = mE + row * 128;
            float acc = __ldg(r + lane)       * sh[lane]
                      + __ldg(r + lane + 32)  * sh[lane + 32]
                      + __ldg(r + lane + 64)  * sh[lane + 64]
                      + __ldg(r + lane + 96)  * sh[lane + 96];
            #pragma unroll
            for (int o = 16; o; o >>= 1) acc += __shfl_xor_sync(0xFFFFFFFFu, acc, o);
            if (lane == 0) g_feat[row] = acc;
        }
    } else {
        pf_resident(dW2, 0);
    }
    grid_bar();

    // ===== Stages 3..5: chain (blocks 0..14); others prefetch =====
    if (blk < 15) mv450_stage(eW1, eb1, g_feat, g_h, true, sh);
    else pf_resident(dW2, 1);
    grid_bar();
    if (blk < 15) mv450_stage(eW2, eb2, g_h, g_feat2, false, sh);
    else pf_resident(dW2, 2);
    grid_bar();
    if (blk < 15) mv450_stage(dW1, db1, g_feat2, g_h2, true, sh);
    else pf_resident(dW2, 3);
    grid_bar();

    // ===== Stage 6: out = dec_W2 @ h2 + db2, TMA-pipelined =====
    {
        float* v = reinterpret_cast<float*>(smem + V_OFF);    // h2 || h2
        for (int i = tid; i < 904; i += NTHR)
            v[i] = (i < 900) ? __ldcg(&g_h2[(i < 450) ? i : (i - 450)]) : 0.f;

        const unsigned mb0 = smem_addr(smem + MB_OFF);
        const unsigned mb1 = mb0 + 8;
        const unsigned sbuf0 = smem_addr(smem + BUF0_OFF);
        const unsigned sbuf1 = smem_addr(smem + BUF1_OFF);
        if (tid == 0) { mbar_init(mb0); mbar_init(mb1); }
        __syncthreads();

        const int pstart = blk * PAIRS_PER_BLK;
        const int pend_i = pstart + PAIRS_PER_BLK;
        const int pend   = (pend_i < NPAIRS) ? pend_i : NPAIRS;
        const int nch    = (pend - pstart + CHUNK - 1) / CHUNK;

        uint64_t pol;
        asm volatile("createpolicy.fractional.L2::evict_first.b64 %0, 1.0;" : "=l"(pol));

        if (tid == 0) {
            fence_async_smem();
            // chunk 0 and 1 (nch >= 2 always: >=415 pairs -> >=14 chunks)
            {
                const int cs = pstart, ce = (cs + CHUNK < pend) ? cs + CHUNK : pend;
                bulk_ld(sbuf0, dW2 + (size_t)cs * 900, (ce - cs) * PAIR_BYTES,
                        mb0, cs >= PR_RES, pol);
            }
            {
                const int cs = pstart + CHUNK;
                const int ce = (cs + CHUNK < pend) ? cs + CHUNK : pend;
                bulk_ld(sbuf1, dW2 + (size_t)cs * 900, (ce - cs) * PAIR_BYTES,
                        mb1, cs >= PR_RES, pol);
            }
        }

        const bool lo16 = (lane < 16);
        const float4* VV = reinterpret_cast<const float4*>(v);
        const float4 v0 = VV[lane];
        const float4 v1 = VV[lane + 32];
        const float4 v2 = VV[lane + 64];
        const float4 v3 = VV[lane + 96];
        const float4 v4 = VV[lane + 128];
        const float4 v5 = VV[lane + 160];
        const float4 v6 = VV[lane + 192];
        const float4 vt = VV[224];

        for (int c = 0; c < nch; ++c) {
            const unsigned mb   = (c & 1) ? mb1 : mb0;
            const char*    bufp = (c & 1) ? (smem + BUF1_OFF) : (smem + BUF0_OFF);
            mbar_wait(mb, (c >> 1) & 1);

            const int cs = pstart + c * CHUNK;
            const int ce = (cs + CHUNK < pend) ? cs + CHUNK : pend;
            const int p  = cs + wid;
            if (wid < CHUNK && p < ce) {
                const float4* wr = reinterpret_cast<const float4*>(bufp) + wid * 225;
                const float4 w0 = wr[lane];
                const float4 w1 = wr[lane + 32];
                const float4 w2 = wr[lane + 64];
                const float4 w3 = wr[lane + 96];
                const float4 w4 = wr[lane + 128];
                const float4 w5 = wr[lane + 160];
                const float4 w6 = wr[lane + 192];

                float acc0 = w0.x*v0.x + w0.y*v0.y + w0.z*v0.z + w0.w*v0.w
                           + w1.x*v1.x + w1.y*v1.y + w1.z*v1.z + w1.w*v1.w
                           + w2.x*v2.x + w2.y*v2.y + w2.z*v2.z + w2.w*v2.w;
                float acc1 = w4.x*v4.x + w4.y*v4.y + w4.z*v4.z + w4.w*v4.w
                           + w5.x*v5.x + w5.y*v5.y + w5.z*v5.z + w5.w*v5.w
                           + w6.x*v6.x + w6.y*v6.y + w6.z*v6.z + w6.w*v6.w;
                {   // straddle: float4 idx lane+96; split at lane 16
                    const float dlo = w3.x*v3.x + w3.y*v3.y;
                    const float dhi = w3.z*v3.z + w3.w*v3.w;
                    acc0 += lo16 ? (dlo + dhi) : ((lane == 16) ? dlo : 0.f);
                    acc1 += (!lo16 && lane != 16) ? (dlo + dhi) : ((lane == 16) ? dhi : 0.f);
                }
                if (lane == 0) {
                    const float4 wt = wr[224];
                    acc1 += wt.x*vt.x + wt.y*vt.y + wt.z*vt.z + wt.w*vt.w;
                }
                // 5-shuffle dual reduction: lane0 <- sum(acc0), lane16 <- sum(acc1)
                float z = lo16 ? acc0 : acc1;
                z += __shfl_xor_sync(0xFFFFFFFFu, lo16 ? acc1 : acc0, 16);
                #pragma unroll
                for (int o = 8; o; o >>= 1) z += __shfl_xor_sync(0xFFFFFFFFu, z, o);

                if (lane == 0)  out[2 * p]     = z + __ldg(db2 + 2 * p);
                if (lane == 16) out[2 * p + 1] = z + __ldg(db2 + 2 * p + 1);
            }
            __syncthreads();               // all warps done with this buffer
            if (tid == 0 && c + 2 < nch) {
                const int ns = pstart + (c + 2) * CHUNK;
                const int ne = (ns + CHUNK < pend) ? ns + CHUNK : pend;
                fence_async_smem();
                bulk_ld((c & 1) ? sbuf1 : sbuf0, dW2 + (size_t)ns * 900,
                        (ne - ns) * PAIR_BYTES, mb, ns >= PR_RES, pol);
            }
        }
    }
}

// ---------------------------------------------------------------------------
// Inputs: x, t, TwE, PE, CE, mE, ext_W1, ext_b1, ext_W2, ext_b2,
//         dec_W1, dec_b1, dec_W2, dec_b2
// ---------------------------------------------------------------------------
extern "C" void kernel_launch(void* const* d_in, const int* in_sizes, int n_in,
                              void* d_out, int out_size)
{
    const float* x   = (const float*)d_in[0];
    const float* TwE = (const float*)d_in[2];
    const float* PE  = (const float*)d_in[3];
    const float* CE  = (const float*)d_in[4];
    const float* mE  = (const float*)d_in[5];
    const float* eW1 = (const float*)d_in[6];
    const float* eb1 = (const float*)d_in[7];
    const float* eW2 = (const float*)d_in[8];
    const float* eb2 = (const float*)d_in[9];
    const float* dW1 = (const float*)d_in[10];
    const float* db1 = (const float*)d_in[11];
    const float* dW2 = (const float*)d_in[12];
    const float* db2 = (const float*)d_in[13];
    float* out = (float*)d_out;

    const int xoff = in_sizes[0] - 4 * 256 * 128;

    static bool attr_set = false;
    if (!attr_set) {
        cudaFuncSetAttribute(fused_kernel,
                             cudaFuncAttributeMaxDynamicSharedMemorySize,
                             SMEM_BYTES);
        attr_set = true;
    }

    fused_kernel<<<NBLK, NTHR, SMEM_BYTES>>>(x, TwE, PE, CE, mE,
                                             eW1, eb1, eW2, eb2,
                                             dW1, db1, dW2, db2,
                                             out, xoff);
    (void)n_in; (void)out_size;
}